// round 14
// baseline (speedup 1.0000x reference)
#include <cuda_runtime.h>
#include <cuda_bf16.h>

// InteractingLayer (AutoInt): B=4096, F=50, E=64, H=4, D=32.
// v8: 1 batch/CTA (M=64), 256 threads, 108KB smem -> 2 CTAs/SM.
// All-tensor (mma.sync bf16-split). Q stays in registers (D-frag -> A-frag
// repack); V drains to Vt^T at its proj stage; scores/softmax/AV barrier-free.
// W staged in K-halves, cp.async double-buffered (8 half-stages).

#define BB 4096
#define FF 50
#define EE 64
#define CC 128

typedef unsigned short u16;
typedef unsigned int u32;

// ---- smem byte offsets ----
#define XH_B 0             // X hi [64][72] bf16 (9216)
#define XL_B 9216          // X lo
#define B0_B 18432         // W half-stage buf0 (20480: hi [128][40], lo at +10240)
#define KH_B 38912         // K image hi [64][136] bf16 (17408)
#define KL_B 56320         // K image lo
#define B1_B 73728         // W half-stage buf1 (inside Vt region; dead after hs5)
#define VTH_B 73728        // Vt hi [128 d][72 g] bf16 (18432)
#define VTL_B 92160        // Vt lo
#define SMEM_BYTES 110592  // x2 CTAs = 221184 <= 228KB/SM
#define X_STRIDE 144
#define W_STRIDE 80        // 40 bf16/row -> conflict-free ldsm
#define K_STRIDE 272
#define VT_STRIDE 144

__device__ u16 g_Wimg[4][16384];  // [w][kh][hl][n][kk] u16

// ---- helpers ----
__device__ __forceinline__ u32 s2u32(const void* p) {
    u32 a; asm("{ .reg .u64 t; cvta.to.shared.u64 t, %1; cvt.u32.u64 %0, t; }" : "=r"(a) : "l"(p));
    return a;
}
__device__ __forceinline__ void ldsm4(u32* r, u32 a) {
    asm volatile("ldmatrix.sync.aligned.m8n8.x4.shared.b16 {%0,%1,%2,%3}, [%4];"
        : "=r"(r[0]), "=r"(r[1]), "=r"(r[2]), "=r"(r[3]) : "r"(a));
}
__device__ __forceinline__ void ldsm2(u32* r, u32 a) {
    asm volatile("ldmatrix.sync.aligned.m8n8.x2.shared.b16 {%0,%1}, [%2];"
        : "=r"(r[0]), "=r"(r[1]) : "r"(a));
}
__device__ __forceinline__ void mma_bf16(float* d, const u32* a, const u32* b) {
    asm volatile("mma.sync.aligned.m16n8k16.row.col.f32.bf16.bf16.f32 "
        "{%0,%1,%2,%3}, {%4,%5,%6,%7}, {%8,%9}, {%0,%1,%2,%3};"
        : "+f"(d[0]), "+f"(d[1]), "+f"(d[2]), "+f"(d[3])
        : "r"(a[0]), "r"(a[1]), "r"(a[2]), "r"(a[3]), "r"(b[0]), "r"(b[1]));
}
__device__ __forceinline__ u32 cvt_bf2(float lo, float hi) {
    u32 r; asm("cvt.rn.bf16x2.f32 %0, %1, %2;" : "=r"(r) : "f"(hi), "f"(lo));
    return r;
}
__device__ __forceinline__ void cp16(u32 dst, const void* src) {
    asm volatile("cp.async.cg.shared.global [%0], [%1], 16;" :: "r"(dst), "l"(src) : "memory");
}
#define CP_COMMIT() asm volatile("cp.async.commit_group;" ::: "memory")
#define CP_WAIT(n)  asm volatile("cp.async.wait_group %0;" :: "n"(n) : "memory")

// stage one W K-half (16KB data) into a strided smem buffer
__device__ __forceinline__ void issue_half(int w, int kh, u32 smb, u32 bufB, int tid) {
    const char* src = (const char*)g_Wimg + (size_t)w * 32768 + (size_t)kh * 16384;
    #pragma unroll
    for (int v = 0; v < 4; ++v) {
        int i = tid + 256 * v;                 // 1024 chunks of 16B
        int hl = i >> 9, n = (i >> 2) & 127, j = i & 3;
        cp16(smb + bufB + (u32)hl * 10240 + (u32)n * W_STRIDE + (u32)j * 16,
             src + hl * 8192 + n * 64 + j * 16);
    }
}

// ---- prep: W^T bf16 hi|lo images, [w][kh][hl][n][kk] ----
__global__ void prep_w(const float* __restrict__ Wq, const float* __restrict__ Wk,
                       const float* __restrict__ Wv, const float* __restrict__ Wr)
{
    int idx = blockIdx.x * blockDim.x + threadIdx.x;
    if (idx >= 32768) return;
    int w = idx >> 13, rem = idx & 8191;
    int n = rem >> 6, k = rem & 63;
    const float* W = (w == 0) ? Wq : (w == 1) ? Wk : (w == 2) ? Wv : Wr;
    float v = W[k * CC + n];
    __nv_bfloat16 h = __float2bfloat16(v);
    __nv_bfloat16 l = __float2bfloat16(v - __bfloat162float(h));
    int kh = k >> 5, kk = k & 31;
    g_Wimg[w][kh * 8192 +        n * 32 + kk] = __bfloat16_as_ushort(h);
    g_Wimg[w][kh * 8192 + 4096 + n * 32 + kk] = __bfloat16_as_ushort(l);
}

__global__ void __launch_bounds__(256, 2)
autoint_v8(const float* __restrict__ X, float* __restrict__ out)
{
    extern __shared__ float sm[];
    char* smc = (char*)sm;
    const int tid  = threadIdx.x;
    const int bid  = blockIdx.x;              // one batch per CTA
    const int lane = tid & 31;
    const int wid  = tid >> 5;                // 0..7
    const int l3   = lane & 3;
    const u32 smb  = s2u32(sm);

    const int ng = wid & 3;                   // head / col group
    const int mg = wid >> 2;                  // row group
    const int m0 = 32 * mg + (lane >> 2);
    const int brow = lane & 7;
    const u32 bkc  = 16 * ((lane >> 3) & 1);
    const int ii   = lane >> 3;

    // stage order: K, R, V, Q  (Q last -> D-frags feed scores directly)
    const int WIMG[4] = {1, 3, 2, 0};
    const u32 BSEL[8] = {B0_B, B1_B, B0_B, B1_B, B0_B, B1_B, B0_B, B0_B};

    // ---- prefetch hs0, build X, prefetch hs1
    issue_half(WIMG[0], 0, smb, B0_B, tid);
    CP_COMMIT();
    {
        u16* XH = (u16*)(smc + XH_B);
        u16* XL = (u16*)(smc + XL_B);
        const float* Xg = X + (size_t)bid * (FF * EE);
        for (int i = tid; i < 4096; i += 256) {
            int r = i >> 6, k = i & 63;
            float v = (r < FF) ? Xg[r * EE + k] : 0.f;
            u16 h = __bfloat16_as_ushort(__float2bfloat16(v));
            u16 l = __bfloat16_as_ushort(__float2bfloat16(v - __uint_as_float((u32)h << 16)));
            XH[r * 72 + k] = h;
            XL[r * 72 + k] = l;
        }
    }
    issue_half(WIMG[0], 1, smb, B1_B, tid);
    CP_COMMIT();

    // ---- 8 half-stages of projections
    float acc[4][8];                          // after hs7 this holds Q D-frags
    u32 ahi[2][4][4], alo[2][4][4];
    float* outB = out + (size_t)bid * (FF * CC);

    for (int hs = 0; hs < 8; ++hs) {
        if (hs < 6) { CP_WAIT(1); } else { CP_WAIT(0); }
        __syncthreads();
        const int w = hs >> 1, kh = hs & 1;

        if (kh == 0) {
            #pragma unroll
            for (int mt = 0; mt < 2; ++mt) {
                const u32 rb = (u32)(32 * mg + 16 * mt + (lane & 15)) * X_STRIDE
                             + 16 * (lane >> 4);
                #pragma unroll
                for (int ksg = 0; ksg < 4; ++ksg) {
                    ldsm4(ahi[mt][ksg], smb + XH_B + rb + 32 * ksg);
                    ldsm4(alo[mt][ksg], smb + XL_B + rb + 32 * ksg);
                }
            }
            #pragma unroll
            for (int nt = 0; nt < 4; ++nt)
                #pragma unroll
                for (int j = 0; j < 8; ++j) acc[nt][j] = 0.f;
        }

        const u32 bb = smb + BSEL[hs];
        #pragma unroll
        for (int nt = 0; nt < 4; ++nt) {
            const u32 rb = (u32)(32 * ng + 8 * nt + brow) * W_STRIDE + bkc;
            #pragma unroll
            for (int ks = 0; ks < 2; ++ks) {
                u32 bh[2], bl[2];
                ldsm2(bh, bb + rb + 32 * ks);
                ldsm2(bl, bb + 10240 + rb + 32 * ks);
                const int ksg = 2 * kh + ks;
                mma_bf16(acc[nt],     ahi[0][ksg], bh);
                mma_bf16(acc[nt],     ahi[0][ksg], bl);
                mma_bf16(acc[nt],     alo[0][ksg], bh);
                mma_bf16(acc[nt] + 4, ahi[1][ksg], bh);
                mma_bf16(acc[nt] + 4, ahi[1][ksg], bl);
                mma_bf16(acc[nt] + 4, alo[1][ksg], bh);
            }
        }
        __syncthreads();                      // buf reads done

        if (hs <= 4) { issue_half(WIMG[(hs + 2) >> 1], (hs + 2) & 1, smb, BSEL[hs + 2], tid); CP_COMMIT(); }
        if (hs == 6) { issue_half(WIMG[3], 1, smb, B0_B, tid); CP_COMMIT(); }

        if (kh == 1) {
            if (w == 0) {
                // K -> bf16 hi|lo image [g][136]
                #pragma unroll
                for (int nt = 0; nt < 4; ++nt) {
                    const int nb = 32 * ng + 8 * nt + 2 * l3;
                    #pragma unroll
                    for (int q = 0; q < 4; ++q) {
                        int r = m0 + 16 * (q >> 1) + 8 * (q & 1);
                        float va = acc[nt][4 * (q >> 1) + 2 * (q & 1)];
                        float vb = acc[nt][4 * (q >> 1) + 2 * (q & 1) + 1];
                        u32 hp = cvt_bf2(va, vb);
                        u32 lp = cvt_bf2(va - __uint_as_float(hp << 16),
                                         vb - __uint_as_float(hp & 0xffff0000u));
                        *(u32*)(smc + KH_B + (u32)r * K_STRIDE + nb * 2) = hp;
                        *(u32*)(smc + KL_B + (u32)r * K_STRIDE + nb * 2) = lp;
                    }
                }
            } else if (w == 1) {
                // residual R -> gmem (epilogue RMWs)
                #pragma unroll
                for (int nt = 0; nt < 4; ++nt) {
                    const int nb = 32 * ng + 8 * nt + 2 * l3;
                    #pragma unroll
                    for (int q = 0; q < 4; ++q) {
                        int r = m0 + 16 * (q >> 1) + 8 * (q & 1);
                        if (r < FF) {
                            float2 v;
                            v.x = acc[nt][4 * (q >> 1) + 2 * (q & 1)];
                            v.y = acc[nt][4 * (q >> 1) + 2 * (q & 1) + 1];
                            *(float2*)(outB + r * CC + nb) = v;
                        }
                    }
                }
            } else if (w == 2) {
                // V -> Vt^T bf16 hi|lo [d][72] (rows g>=50 are exact zeros)
                #pragma unroll
                for (int nt = 0; nt < 4; ++nt) {
                    const int n0 = 32 * ng + 8 * nt + 2 * l3;
                    #pragma unroll
                    for (int q = 0; q < 4; ++q) {
                        int g = m0 + 16 * (q >> 1) + 8 * (q & 1);
                        float va = acc[nt][4 * (q >> 1) + 2 * (q & 1)];
                        float vb = acc[nt][4 * (q >> 1) + 2 * (q & 1) + 1];
                        u16 ha = __bfloat16_as_ushort(__float2bfloat16(va));
                        u16 hb = __bfloat16_as_ushort(__float2bfloat16(vb));
                        u16 la = __bfloat16_as_ushort(__float2bfloat16(va - __uint_as_float((u32)ha << 16)));
                        u16 lb = __bfloat16_as_ushort(__float2bfloat16(vb - __uint_as_float((u32)hb << 16)));
                        u32 base = (u32)g * 2;
                        *(u16*)(smc + VTH_B + base + (u32)n0 * VT_STRIDE)       = ha;
                        *(u16*)(smc + VTH_B + base + (u32)(n0 + 1) * VT_STRIDE) = hb;
                        *(u16*)(smc + VTL_B + base + (u32)n0 * VT_STRIDE)       = la;
                        *(u16*)(smc + VTL_B + base + (u32)(n0 + 1) * VT_STRIDE) = lb;
                    }
                }
            }
            // w == 3 (Q): keep acc as dQ
        }
    }
    // after hs7's sync: K image, Vt, R all visible; Q in acc. No more barriers.

    // ---- scores: warp (mg,ng) = rows 32*mg, head ng; N=64 g, K=32 d
    float dS[2][8][4];
    #pragma unroll
    for (int mt = 0; mt < 2; ++mt)
        #pragma unroll
        for (int nt = 0; nt < 8; ++nt)
            #pragma unroll
            for (int j = 0; j < 4; ++j) dS[mt][nt][j] = 0.f;

    #pragma unroll
    for (int kb = 0; kb < 2; ++kb) {
        // repack Q D-frags -> bf16 hi|lo A-frags (v7-validated mapping)
        u32 qH[2][4], qL[2][4];
        #pragma unroll
        for (int mt = 0; mt < 2; ++mt)
            #pragma unroll
            for (int j = 0; j < 4; ++j) {
                int nt = 2 * kb + (j >> 1);
                float x0 = acc[nt][4 * mt + 2 * (j & 1)];
                float x1 = acc[nt][4 * mt + 2 * (j & 1) + 1];
                u32 hp = cvt_bf2(x0, x1);
                qH[mt][j] = hp;
                qL[mt][j] = cvt_bf2(x0 - __uint_as_float(hp << 16),
                                    x1 - __uint_as_float(hp & 0xffff0000u));
            }
        #pragma unroll
        for (int p = 0; p < 4; ++p) {
            u32 bh4[4], bl4[4];
            u32 kd = smb + KH_B + (u32)(8 * (2 * p + (ii >> 1)) + (lane & 7)) * K_STRIDE
                   + 64 * ng + kb * 32 + 16 * (ii & 1);
            ldsm4(bh4, kd);
            ldsm4(bl4, kd + (KL_B - KH_B));
            #pragma unroll
            for (int mt = 0; mt < 2; ++mt)
                #pragma unroll
                for (int ntl = 0; ntl < 2; ++ntl) {
                    float* d = dS[mt][2 * p + ntl];
                    mma_bf16(d, qH[mt], &bh4[2 * ntl]);
                    mma_bf16(d, qL[mt], &bh4[2 * ntl]);
                    mma_bf16(d, qH[mt], &bl4[2 * ntl]);
                }
        }
    }

    // ---- softmax in fragments (mask cols >= 50)
    #pragma unroll
    for (int mt = 0; mt < 2; ++mt)
        #pragma unroll
        for (int qq = 0; qq < 2; ++qq) {
            float mx = -3.4e38f;
            #pragma unroll
            for (int nt = 0; nt < 8; ++nt)
                #pragma unroll
                for (int c = 0; c < 2; ++c) {
                    bool ok = (nt < 6) || (nt == 6 && l3 == 0);
                    if (ok) mx = fmaxf(mx, dS[mt][nt][2 * qq + c]);
                }
            mx = fmaxf(mx, __shfl_xor_sync(0xffffffffu, mx, 1));
            mx = fmaxf(mx, __shfl_xor_sync(0xffffffffu, mx, 2));
            float su = 0.f;
            #pragma unroll
            for (int nt = 0; nt < 8; ++nt)
                #pragma unroll
                for (int c = 0; c < 2; ++c) {
                    bool ok = (nt < 6) || (nt == 6 && l3 == 0);
                    float e = ok ? __expf(dS[mt][nt][2 * qq + c] - mx) : 0.f;
                    dS[mt][nt][2 * qq + c] = e;
                    su += e;
                }
            su += __shfl_xor_sync(0xffffffffu, su, 1);
            su += __shfl_xor_sync(0xffffffffu, su, 2);
            float inv = 1.0f / su;
            #pragma unroll
            for (int nt = 0; nt < 8; ++nt) {
                dS[mt][nt][2 * qq]     *= inv;
                dS[mt][nt][2 * qq + 1] *= inv;
            }
        }

    // ---- AV: lazy repack attn -> A-frags; B = Vt[d][g]; M=32,N=32,K=64
    float dV[2][4][4];
    #pragma unroll
    for (int mt = 0; mt < 2; ++mt)
        #pragma unroll
        for (int nt = 0; nt < 4; ++nt)
            #pragma unroll
            for (int j = 0; j < 4; ++j) dV[mt][nt][j] = 0.f;

    #pragma unroll
    for (int kb2 = 0; kb2 < 4; ++kb2) {
        u32 pH[2][4], pL[2][4];
        #pragma unroll
        for (int mt = 0; mt < 2; ++mt)
            #pragma unroll
            for (int j = 0; j < 4; ++j) {
                int nt = 2 * kb2 + (j >> 1);
                float x0 = dS[mt][nt][2 * (j & 1)];
                float x1 = dS[mt][nt][2 * (j & 1) + 1];
                u32 hp = cvt_bf2(x0, x1);
                pH[mt][j] = hp;
                pL[mt][j] = cvt_bf2(x0 - __uint_as_float(hp << 16),
                                    x1 - __uint_as_float(hp & 0xffff0000u));
            }
        #pragma unroll
        for (int p = 0; p < 2; ++p) {
            u32 bh4[4], bl4[4];
            u32 vd = smb + VTH_B
                   + (u32)(32 * ng + 8 * (2 * p + (ii >> 1)) + (lane & 7)) * VT_STRIDE
                   + kb2 * 32 + 16 * (ii & 1);
            ldsm4(bh4, vd);
            ldsm4(bl4, vd + (VTL_B - VTH_B));
            #pragma unroll
            for (int mt = 0; mt < 2; ++mt)
                #pragma unroll
                for (int ntl = 0; ntl < 2; ++ntl) {
                    float* d = dV[mt][2 * p + ntl];
                    mma_bf16(d, pH[mt], &bh4[2 * ntl]);
                    mma_bf16(d, pL[mt], &bh4[2 * ntl]);
                    mma_bf16(d, pH[mt], &bl4[2 * ntl]);
                }
        }
    }

    // ---- epilogue: out = relu(AV + R)  (R pre-stored in out)
    #pragma unroll
    for (int mt = 0; mt < 2; ++mt)
        #pragma unroll
        for (int qq = 0; qq < 2; ++qq) {
            int fl = 32 * mg + 16 * mt + 8 * qq + (lane >> 2);
            if (fl < FF) {
                #pragma unroll
                for (int nt = 0; nt < 4; ++nt) {
                    int col = 32 * ng + 8 * nt + 2 * l3;
                    float2* p = (float2*)(outB + fl * CC + col);
                    float2 rv = *p;
                    float2 o;
                    o.x = fmaxf(dV[mt][nt][2 * qq]     + rv.x, 0.f);
                    o.y = fmaxf(dV[mt][nt][2 * qq + 1] + rv.y, 0.f);
                    *p = o;
                }
            }
        }
}

extern "C" void kernel_launch(void* const* d_in, const int* in_sizes, int n_in,
                              void* d_out, int out_size)
{
    const float* X  = (const float*)d_in[0];
    const float* Wq = (const float*)d_in[1];
    const float* Wk = (const float*)d_in[2];
    const float* Wv = (const float*)d_in[3];
    const float* Wr = (const float*)d_in[4];
    float* out = (float*)d_out;

    prep_w<<<64, 512>>>(Wq, Wk, Wv, Wr);
    cudaFuncSetAttribute(autoint_v8,
                         cudaFuncAttributeMaxDynamicSharedMemorySize, SMEM_BYTES);
    autoint_v8<<<BB, 256, SMEM_BYTES>>>(X, out);
}

// round 15
// speedup vs baseline: 1.3553x; 1.3553x over previous
#include <cuda_runtime.h>
#include <cuda_bf16.h>

// InteractingLayer (AutoInt): B=4096, F=50, E=64, H=4, D=32.
// v9 = v7 shape (2 batches/CTA, 512 thr, 2048 CTAs; cp.async double-buffered W)
//    + v8 wins (Q in regs via D->A repack; V drains to Vt^T in-stage;
//      barrier-free tail), enabled by batch-padded A rows (b0: 0..63, b1: 64..127).
// All-tensor mma.sync bf16-split. 180KB smem, 1 CTA/SM.

#define BB 4096
#define FF 50
#define EE 64
#define CC 128

typedef unsigned short u16;
typedef unsigned int u32;

// ---- smem byte offsets ----
#define XH_B 0             // X hi [128][72] bf16 (18432)
#define XL_B 18432         // X lo
#define WB0_B 36864        // W stage buf0: hi [128][72], lo at +18432 (36864)
#define WB1_B 73728        // W stage buf1
#define KH_B 110592        // K image hi [128][136] (34816)
#define KL_B 145408        // K image lo
#define SMEM_BYTES 180224
// Vt overlays X + WB0 after stage V: hi [2 bt][128 d][72 g] @0, lo @36864
#define VTH_B 0
#define VTL_B 36864
#define VT_BT 18432
#define X_STRIDE 144
#define K_STRIDE 272
#define VT_STRIDE 144

__device__ u16 g_Wimg[4][2 * 128 * 64];   // [w][hi|lo][n][k] bf16 of W^T

// ---- helpers ----
__device__ __forceinline__ u32 s2u32(const void* p) {
    u32 a; asm("{ .reg .u64 t; cvta.to.shared.u64 t, %1; cvt.u32.u64 %0, t; }" : "=r"(a) : "l"(p));
    return a;
}
__device__ __forceinline__ void ldsm4(u32* r, u32 a) {
    asm volatile("ldmatrix.sync.aligned.m8n8.x4.shared.b16 {%0,%1,%2,%3}, [%4];"
        : "=r"(r[0]), "=r"(r[1]), "=r"(r[2]), "=r"(r[3]) : "r"(a));
}
__device__ __forceinline__ void ldsm2(u32* r, u32 a) {
    asm volatile("ldmatrix.sync.aligned.m8n8.x2.shared.b16 {%0,%1}, [%2];"
        : "=r"(r[0]), "=r"(r[1]) : "r"(a));
}
__device__ __forceinline__ void mma_bf16(float* d, const u32* a, const u32* b) {
    asm volatile("mma.sync.aligned.m16n8k16.row.col.f32.bf16.bf16.f32 "
        "{%0,%1,%2,%3}, {%4,%5,%6,%7}, {%8,%9}, {%0,%1,%2,%3};"
        : "+f"(d[0]), "+f"(d[1]), "+f"(d[2]), "+f"(d[3])
        : "r"(a[0]), "r"(a[1]), "r"(a[2]), "r"(a[3]), "r"(b[0]), "r"(b[1]));
}
__device__ __forceinline__ u32 cvt_bf2(float lo, float hi) {
    u32 r; asm("cvt.rn.bf16x2.f32 %0, %1, %2;" : "=r"(r) : "f"(hi), "f"(lo));
    return r;
}
__device__ __forceinline__ void cp16(u32 dst, const void* src) {
    asm volatile("cp.async.cg.shared.global [%0], [%1], 16;" :: "r"(dst), "l"(src) : "memory");
}
#define CP_COMMIT() asm volatile("cp.async.commit_group;" ::: "memory")
#define CP_WAIT(n)  asm volatile("cp.async.wait_group %0;" :: "n"(n) : "memory")

// stage one W (32KB) into smem buffer (hi at bufB, lo at +18432)
__device__ __forceinline__ void issue_w(const u16* img, u32 smb, u32 bufB, int tid) {
    const char* src = (const char*)img;
    #pragma unroll
    for (int v = 0; v < 4; ++v) {
        int i = tid + 512 * v;
        int ss = i >> 10, n = (i >> 3) & 127, j = i & 7;
        cp16(smb + bufB + (u32)ss * 18432 + (u32)n * X_STRIDE + (u32)j * 16,
             src + (size_t)i * 16);
    }
}

// ---- prep: W^T bf16 hi|lo images in [n][k] layout ----
__global__ void prep_w(const float* __restrict__ Wq, const float* __restrict__ Wk,
                       const float* __restrict__ Wv, const float* __restrict__ Wr)
{
    int idx = blockIdx.x * blockDim.x + threadIdx.x;
    if (idx >= 32768) return;
    int w = idx >> 13, rem = idx & 8191;
    int n = rem >> 6, k = rem & 63;
    const float* W = (w == 0) ? Wq : (w == 1) ? Wk : (w == 2) ? Wv : Wr;
    float v = W[k * CC + n];
    __nv_bfloat16 h = __float2bfloat16(v);
    __nv_bfloat16 l = __float2bfloat16(v - __bfloat162float(h));
    g_Wimg[w][n * 64 + k]        = __bfloat16_as_ushort(h);
    g_Wimg[w][8192 + n * 64 + k] = __bfloat16_as_ushort(l);
}

__global__ void __launch_bounds__(512, 1)
autoint_v9(const float* __restrict__ X, float* __restrict__ out)
{
    extern __shared__ float sm[];
    char* smc = (char*)sm;
    const int tid  = threadIdx.x;
    const int bid  = blockIdx.x;              // batches 2*bid, 2*bid+1
    const int lane = tid & 31;
    const int wid  = tid >> 5;                // 0..15
    const int l3   = lane & 3;
    const u32 smb  = s2u32(sm);

    const int ng = wid & 3;                   // col group / head
    const int mg = wid >> 2;                  // row group: bt = mg>>1, sub = mg&1
    const int sbt = mg >> 1;
    const int sub = mg & 1;
    const int m0  = 32 * mg + (lane >> 2);
    const int brow = lane & 7;
    const u32 bkc  = 16 * ((lane >> 3) & 1);
    const int ii   = lane >> 3;

    // stage order: K(buf0), R(buf1), V(buf0), Q(buf1)
    const int WIMG[4] = {1, 3, 2, 0};
    const u32 BUFB[4] = {WB0_B, WB1_B, WB0_B, WB1_B};

    // ---- prefetch K-stage W, build batch-padded X image
    issue_w(g_Wimg[WIMG[0]], smb, BUFB[0], tid);
    CP_COMMIT();
    {
        u16* XH = (u16*)(smc + XH_B);
        u16* XL = (u16*)(smc + XL_B);
        const float* Xg = X + (size_t)(2 * bid) * (FF * EE);
        for (int i = tid; i < 8192; i += 512) {
            int r = i >> 6, k = i & 63;
            int bt = r >> 6, f = r & 63;      // rows 0..63 = b0, 64..127 = b1
            float v = (f < FF) ? Xg[(bt * FF + f) * EE + k] : 0.f;
            u16 h = __bfloat16_as_ushort(__float2bfloat16(v));
            u16 l = __bfloat16_as_ushort(__float2bfloat16(v - __uint_as_float((u32)h << 16)));
            XH[r * 72 + k] = h;
            XL[r * 72 + k] = l;
        }
    }
    __syncthreads();

    // ---- A fragments once (held through all stages)
    u32 ahi[2][4][4], alo[2][4][4];
    #pragma unroll
    for (int mt = 0; mt < 2; ++mt) {
        const u32 rb = (u32)(32 * mg + 16 * mt + (lane & 15)) * X_STRIDE + 16 * (lane >> 4);
        #pragma unroll
        for (int ks = 0; ks < 4; ++ks) {
            ldsm4(ahi[mt][ks], smb + XH_B + rb + 32 * ks);
            ldsm4(alo[mt][ks], smb + XL_B + rb + 32 * ks);
        }
    }
    issue_w(g_Wimg[WIMG[1]], smb, BUFB[1], tid);
    CP_COMMIT();

    float acc[4][8];                          // after s3 holds Q D-frags
    float* outB0 = out + (size_t)(2 * bid) * (FF * CC);

    for (int s = 0; s < 4; ++s) {
        if (s == 3) { CP_WAIT(0); } else { CP_WAIT(1); }
        __syncthreads();

        #pragma unroll
        for (int nt = 0; nt < 4; ++nt)
            #pragma unroll
            for (int j = 0; j < 8; ++j) acc[nt][j] = 0.f;

        const u32 bb = smb + BUFB[s];
        #pragma unroll
        for (int nt = 0; nt < 4; ++nt) {
            const u32 rb = (u32)(32 * ng + 8 * nt + brow) * X_STRIDE + bkc;
            #pragma unroll
            for (int ks = 0; ks < 4; ++ks) {
                u32 bh[2], bl[2];
                ldsm2(bh, bb + rb + 32 * ks);
                ldsm2(bl, bb + 18432 + rb + 32 * ks);
                mma_bf16(acc[nt],     ahi[0][ks], bh);
                mma_bf16(acc[nt],     ahi[0][ks], bl);
                mma_bf16(acc[nt],     alo[0][ks], bh);
                mma_bf16(acc[nt] + 4, ahi[1][ks], bh);
                mma_bf16(acc[nt] + 4, ahi[1][ks], bl);
                mma_bf16(acc[nt] + 4, alo[1][ks], bh);
            }
        }

        if (s == 0) {
            // K -> bf16 hi|lo image [128 rows][136] (pad rows are exact zeros)
            #pragma unroll
            for (int nt = 0; nt < 4; ++nt) {
                const int nb = 32 * ng + 8 * nt + 2 * l3;
                #pragma unroll
                for (int q = 0; q < 4; ++q) {
                    int r = m0 + 16 * (q >> 1) + 8 * (q & 1);
                    float va = acc[nt][4 * (q >> 1) + 2 * (q & 1)];
                    float vb = acc[nt][4 * (q >> 1) + 2 * (q & 1) + 1];
                    u32 hp = cvt_bf2(va, vb);
                    u32 lp = cvt_bf2(va - __uint_as_float(hp << 16),
                                     vb - __uint_as_float(hp & 0xffff0000u));
                    *(u32*)(smc + KH_B + (u32)r * K_STRIDE + nb * 2) = hp;
                    *(u32*)(smc + KL_B + (u32)r * K_STRIDE + nb * 2) = lp;
                }
            }
        } else if (s == 1) {
            // residual R -> gmem (epilogue RMWs it)
            #pragma unroll
            for (int nt = 0; nt < 4; ++nt) {
                const int nb = 32 * ng + 8 * nt + 2 * l3;
                #pragma unroll
                for (int q = 0; q < 4; ++q) {
                    int r = m0 + 16 * (q >> 1) + 8 * (q & 1);
                    int bt = r >> 6, f = r & 63;
                    if (f < FF) {
                        float2 v;
                        v.x = acc[nt][4 * (q >> 1) + 2 * (q & 1)];
                        v.y = acc[nt][4 * (q >> 1) + 2 * (q & 1) + 1];
                        *(float2*)(outB0 + (size_t)bt * (FF * CC) + f * CC + nb) = v;
                    }
                }
            }
        }

        if (s < 3) __syncthreads();           // buf reads done before reuse
        if (s < 2) { issue_w(g_Wimg[WIMG[s + 2]], smb, BUFB[s + 2], tid); CP_COMMIT(); }

        if (s == 2) {
            // V -> Vt^T bf16 hi|lo [bt][d][72 g]; overlays X+buf0 (both dead).
            // Pad cols g>=50 get exact zeros automatically (V pad rows are 0).
            #pragma unroll
            for (int nt = 0; nt < 4; ++nt) {
                const int n0 = 32 * ng + 8 * nt + 2 * l3;
                #pragma unroll
                for (int q = 0; q < 4; ++q) {
                    int r = m0 + 16 * (q >> 1) + 8 * (q & 1);
                    int bt = r >> 6, g = r & 63;
                    float va = acc[nt][4 * (q >> 1) + 2 * (q & 1)];
                    float vb = acc[nt][4 * (q >> 1) + 2 * (q & 1) + 1];
                    u16 ha = __bfloat16_as_ushort(__float2bfloat16(va));
                    u16 hb = __bfloat16_as_ushort(__float2bfloat16(vb));
                    u16 la = __bfloat16_as_ushort(__float2bfloat16(va - __uint_as_float((u32)ha << 16)));
                    u16 lb = __bfloat16_as_ushort(__float2bfloat16(vb - __uint_as_float((u32)hb << 16)));
                    u32 base = (u32)bt * VT_BT + (u32)g * 2;
                    *(u16*)(smc + VTH_B + base + (u32)n0 * VT_STRIDE)       = ha;
                    *(u16*)(smc + VTH_B + base + (u32)(n0 + 1) * VT_STRIDE) = hb;
                    *(u16*)(smc + VTL_B + base + (u32)n0 * VT_STRIDE)       = la;
                    *(u16*)(smc + VTL_B + base + (u32)(n0 + 1) * VT_STRIDE) = lb;
                }
            }
        }
    }
    // after s3's top sync: K image + Vt + R all visible; Q in acc. Tail is
    // barrier-free (Vt writes happened before s3's top sync).

    // ---- scores: warp = (bt=sbt, head=ng, row-half sub); N=64 g, K=32 d
    float dS[2][8][4];
    #pragma unroll
    for (int mt = 0; mt < 2; ++mt)
        #pragma unroll
        for (int nt = 0; nt < 8; ++nt)
            #pragma unroll
            for (int j = 0; j < 4; ++j) dS[mt][nt][j] = 0.f;

    #pragma unroll
    for (int kb = 0; kb < 2; ++kb) {
        // repack Q D-frags -> bf16 hi|lo A-frags (validated mapping)
        u32 qH[2][4], qL[2][4];
        #pragma unroll
        for (int mt = 0; mt < 2; ++mt)
            #pragma unroll
            for (int j = 0; j < 4; ++j) {
                int nt = 2 * kb + (j >> 1);
                float x0 = acc[nt][4 * mt + 2 * (j & 1)];
                float x1 = acc[nt][4 * mt + 2 * (j & 1) + 1];
                u32 hp = cvt_bf2(x0, x1);
                qH[mt][j] = hp;
                qL[mt][j] = cvt_bf2(x0 - __uint_as_float(hp << 16),
                                    x1 - __uint_as_float(hp & 0xffff0000u));
            }
        #pragma unroll
        for (int p = 0; p < 4; ++p) {
            u32 bh4[4], bl4[4];
            u32 kd = smb + KH_B
                   + (u32)(64 * sbt + 8 * (2 * p + (ii >> 1)) + (lane & 7)) * K_STRIDE
                   + 64 * ng + kb * 32 + 16 * (ii & 1);
            ldsm4(bh4, kd);
            ldsm4(bl4, kd + (KL_B - KH_B));
            #pragma unroll
            for (int mt = 0; mt < 2; ++mt)
                #pragma unroll
                for (int ntl = 0; ntl < 2; ++ntl) {
                    float* d = dS[mt][2 * p + ntl];
                    mma_bf16(d, qH[mt], &bh4[2 * ntl]);
                    mma_bf16(d, qL[mt], &bh4[2 * ntl]);
                    mma_bf16(d, qH[mt], &bl4[2 * ntl]);
                }
        }
    }

    // ---- softmax in fragments (mask cols >= 50)
    #pragma unroll
    for (int mt = 0; mt < 2; ++mt)
        #pragma unroll
        for (int qq = 0; qq < 2; ++qq) {
            float mx = -3.4e38f;
            #pragma unroll
            for (int nt = 0; nt < 8; ++nt)
                #pragma unroll
                for (int c = 0; c < 2; ++c) {
                    bool ok = (nt < 6) || (nt == 6 && l3 == 0);
                    if (ok) mx = fmaxf(mx, dS[mt][nt][2 * qq + c]);
                }
            mx = fmaxf(mx, __shfl_xor_sync(0xffffffffu, mx, 1));
            mx = fmaxf(mx, __shfl_xor_sync(0xffffffffu, mx, 2));
            float su = 0.f;
            #pragma unroll
            for (int nt = 0; nt < 8; ++nt)
                #pragma unroll
                for (int c = 0; c < 2; ++c) {
                    bool ok = (nt < 6) || (nt == 6 && l3 == 0);
                    float e = ok ? __expf(dS[mt][nt][2 * qq + c] - mx) : 0.f;
                    dS[mt][nt][2 * qq + c] = e;
                    su += e;
                }
            su += __shfl_xor_sync(0xffffffffu, su, 1);
            su += __shfl_xor_sync(0xffffffffu, su, 2);
            float inv = 1.0f / su;
            #pragma unroll
            for (int nt = 0; nt < 8; ++nt) {
                dS[mt][nt][2 * qq]     *= inv;
                dS[mt][nt][2 * qq + 1] *= inv;
            }
        }

    // ---- AV: lazy repack attn -> A-frags; B = Vt[sbt][d][g]; M=32,N=32,K=64
    float dV[2][4][4];
    #pragma unroll
    for (int mt = 0; mt < 2; ++mt)
        #pragma unroll
        for (int nt = 0; nt < 4; ++nt)
            #pragma unroll
            for (int j = 0; j < 4; ++j) dV[mt][nt][j] = 0.f;

    #pragma unroll
    for (int kb2 = 0; kb2 < 4; ++kb2) {
        u32 pH[2][4], pL[2][4];
        #pragma unroll
        for (int mt = 0; mt < 2; ++mt)
            #pragma unroll
            for (int j = 0; j < 4; ++j) {
                int nt = 2 * kb2 + (j >> 1);
                float x0 = dS[mt][nt][2 * (j & 1)];
                float x1 = dS[mt][nt][2 * (j & 1) + 1];
                u32 hp = cvt_bf2(x0, x1);
                pH[mt][j] = hp;
                pL[mt][j] = cvt_bf2(x0 - __uint_as_float(hp << 16),
                                    x1 - __uint_as_float(hp & 0xffff0000u));
            }
        #pragma unroll
        for (int p = 0; p < 2; ++p) {
            u32 bh4[4], bl4[4];
            u32 vd = smb + VTH_B + (u32)sbt * VT_BT
                   + (u32)(32 * ng + 8 * (2 * p + (ii >> 1)) + (lane & 7)) * VT_STRIDE
                   + kb2 * 32 + 16 * (ii & 1);
            ldsm4(bh4, vd);
            ldsm4(bl4, vd + (VTL_B - VTH_B));
            #pragma unroll
            for (int mt = 0; mt < 2; ++mt)
                #pragma unroll
                for (int ntl = 0; ntl < 2; ++ntl) {
                    float* d = dV[mt][2 * p + ntl];
                    mma_bf16(d, pH[mt], &bh4[2 * ntl]);
                    mma_bf16(d, pL[mt], &bh4[2 * ntl]);
                    mma_bf16(d, pH[mt], &bl4[2 * ntl]);
                }
        }
    }

    // ---- epilogue: out = relu(AV + R)  (R pre-stored in out by stage 1)
    {
        float* outB = outB0 + (size_t)sbt * (FF * CC);
        #pragma unroll
        for (int mt = 0; mt < 2; ++mt)
            #pragma unroll
            for (int qq = 0; qq < 2; ++qq) {
                int fl = 32 * sub + 16 * mt + 8 * qq + (lane >> 2);
                if (fl < FF) {
                    #pragma unroll
                    for (int nt = 0; nt < 4; ++nt) {
                        int col = 32 * ng + 8 * nt + 2 * l3;
                        float2* p = (float2*)(outB + fl * CC + col);
                        float2 rv = *p;
                        float2 o;
                        o.x = fmaxf(dV[mt][nt][2 * qq]     + rv.x, 0.f);
                        o.y = fmaxf(dV[mt][nt][2 * qq + 1] + rv.y, 0.f);
                        *p = o;
                    }
                }
            }
    }
}

extern "C" void kernel_launch(void* const* d_in, const int* in_sizes, int n_in,
                              void* d_out, int out_size)
{
    const float* X  = (const float*)d_in[0];
    const float* Wq = (const float*)d_in[1];
    const float* Wk = (const float*)d_in[2];
    const float* Wv = (const float*)d_in[3];
    const float* Wr = (const float*)d_in[4];
    float* out = (float*)d_out;

    prep_w<<<64, 512>>>(Wq, Wk, Wv, Wr);
    cudaFuncSetAttribute(autoint_v9,
                         cudaFuncAttributeMaxDynamicSharedMemorySize, SMEM_BYTES);
    autoint_v9<<<BB / 2, 512, SMEM_BYTES>>>(X, out);
}

// round 16
// speedup vs baseline: 1.3649x; 1.0071x over previous
#include <cuda_runtime.h>
#include <cuda_bf16.h>

// InteractingLayer (AutoInt): B=4096, F=50, E=64, H=4, D=32.
// v10 = v9 + ILP restructure (bitwise-identical numerics):
//   - proj: ks-outer / nt-inner, MMAs issued in chain-position order
//     (RAW distance 2 -> 8), B-frags via ldsm4 (2 n-tiles per load)
//   - scores/AV: chain-position-ordered MMA issue (distance 1 -> 4/8)
// 2 batches/CTA, 512 thr, 2048 CTAs, 180KB smem, cp.async double-buffered W.

#define BB 4096
#define FF 50
#define EE 64
#define CC 128

typedef unsigned short u16;
typedef unsigned int u32;

// ---- smem byte offsets ----
#define XH_B 0             // X hi [128][72] bf16 (18432)
#define XL_B 18432         // X lo
#define WB0_B 36864        // W stage buf0: hi [128][72], lo at +18432
#define WB1_B 73728        // W stage buf1
#define KH_B 110592        // K image hi [128][136] (34816)
#define KL_B 145408        // K image lo
#define SMEM_BYTES 180224
// Vt overlays X + WB0 after stage V: hi [2 bt][128 d][72 g] @0, lo @36864
#define VTH_B 0
#define VTL_B 36864
#define VT_BT 18432
#define X_STRIDE 144
#define K_STRIDE 272
#define VT_STRIDE 144

__device__ u16 g_Wimg[4][2 * 128 * 64];   // [w][hi|lo][n][k] bf16 of W^T

// ---- helpers ----
__device__ __forceinline__ u32 s2u32(const void* p) {
    u32 a; asm("{ .reg .u64 t; cvta.to.shared.u64 t, %1; cvt.u32.u64 %0, t; }" : "=r"(a) : "l"(p));
    return a;
}
__device__ __forceinline__ void ldsm4(u32* r, u32 a) {
    asm volatile("ldmatrix.sync.aligned.m8n8.x4.shared.b16 {%0,%1,%2,%3}, [%4];"
        : "=r"(r[0]), "=r"(r[1]), "=r"(r[2]), "=r"(r[3]) : "r"(a));
}
__device__ __forceinline__ void mma_bf16(float* d, const u32* a, const u32* b) {
    asm volatile("mma.sync.aligned.m16n8k16.row.col.f32.bf16.bf16.f32 "
        "{%0,%1,%2,%3}, {%4,%5,%6,%7}, {%8,%9}, {%0,%1,%2,%3};"
        : "+f"(d[0]), "+f"(d[1]), "+f"(d[2]), "+f"(d[3])
        : "r"(a[0]), "r"(a[1]), "r"(a[2]), "r"(a[3]), "r"(b[0]), "r"(b[1]));
}
__device__ __forceinline__ u32 cvt_bf2(float lo, float hi) {
    u32 r; asm("cvt.rn.bf16x2.f32 %0, %1, %2;" : "=r"(r) : "f"(hi), "f"(lo));
    return r;
}
__device__ __forceinline__ void cp16(u32 dst, const void* src) {
    asm volatile("cp.async.cg.shared.global [%0], [%1], 16;" :: "r"(dst), "l"(src) : "memory");
}
#define CP_COMMIT() asm volatile("cp.async.commit_group;" ::: "memory")
#define CP_WAIT(n)  asm volatile("cp.async.wait_group %0;" :: "n"(n) : "memory")

// stage one W (32KB) into smem buffer (hi at bufB, lo at +18432)
__device__ __forceinline__ void issue_w(const u16* img, u32 smb, u32 bufB, int tid) {
    const char* src = (const char*)img;
    #pragma unroll
    for (int v = 0; v < 4; ++v) {
        int i = tid + 512 * v;
        int ss = i >> 10, n = (i >> 3) & 127, j = i & 7;
        cp16(smb + bufB + (u32)ss * 18432 + (u32)n * X_STRIDE + (u32)j * 16,
             src + (size_t)i * 16);
    }
}

// ---- prep: W^T bf16 hi|lo images in [n][k] layout ----
__global__ void prep_w(const float* __restrict__ Wq, const float* __restrict__ Wk,
                       const float* __restrict__ Wv, const float* __restrict__ Wr)
{
    int idx = blockIdx.x * blockDim.x + threadIdx.x;
    if (idx >= 32768) return;
    int w = idx >> 13, rem = idx & 8191;
    int n = rem >> 6, k = rem & 63;
    const float* W = (w == 0) ? Wq : (w == 1) ? Wk : (w == 2) ? Wv : Wr;
    float v = W[k * CC + n];
    __nv_bfloat16 h = __float2bfloat16(v);
    __nv_bfloat16 l = __float2bfloat16(v - __bfloat162float(h));
    g_Wimg[w][n * 64 + k]        = __bfloat16_as_ushort(h);
    g_Wimg[w][8192 + n * 64 + k] = __bfloat16_as_ushort(l);
}

__global__ void __launch_bounds__(512, 1)
autoint_v10(const float* __restrict__ X, float* __restrict__ out)
{
    extern __shared__ float sm[];
    char* smc = (char*)sm;
    const int tid  = threadIdx.x;
    const int bid  = blockIdx.x;              // batches 2*bid, 2*bid+1
    const int lane = tid & 31;
    const int wid  = tid >> 5;                // 0..15
    const int l3   = lane & 3;
    const u32 smb  = s2u32(sm);

    const int ng = wid & 3;                   // col group / head
    const int mg = wid >> 2;                  // row group: bt = mg>>1, sub = mg&1
    const int sbt = mg >> 1;
    const int sub = mg & 1;
    const int m0  = 32 * mg + (lane >> 2);
    const int ii  = lane >> 3;

    // stage order: K(buf0), R(buf1), V(buf0), Q(buf1)
    const int WIMG[4] = {1, 3, 2, 0};
    const u32 BUFB[4] = {WB0_B, WB1_B, WB0_B, WB1_B};

    // ---- prefetch K-stage W, build batch-padded X image
    issue_w(g_Wimg[WIMG[0]], smb, BUFB[0], tid);
    CP_COMMIT();
    {
        u16* XH = (u16*)(smc + XH_B);
        u16* XL = (u16*)(smc + XL_B);
        const float* Xg = X + (size_t)(2 * bid) * (FF * EE);
        for (int i = tid; i < 8192; i += 512) {
            int r = i >> 6, k = i & 63;
            int bt = r >> 6, f = r & 63;      // rows 0..63 = b0, 64..127 = b1
            float v = (f < FF) ? Xg[(bt * FF + f) * EE + k] : 0.f;
            u16 h = __bfloat16_as_ushort(__float2bfloat16(v));
            u16 l = __bfloat16_as_ushort(__float2bfloat16(v - __uint_as_float((u32)h << 16)));
            XH[r * 72 + k] = h;
            XL[r * 72 + k] = l;
        }
    }
    __syncthreads();

    // ---- A fragments once (held through all stages)
    u32 ahi[2][4][4], alo[2][4][4];
    #pragma unroll
    for (int mt = 0; mt < 2; ++mt) {
        const u32 rb = (u32)(32 * mg + 16 * mt + (lane & 15)) * X_STRIDE + 16 * (lane >> 4);
        #pragma unroll
        for (int ks = 0; ks < 4; ++ks) {
            ldsm4(ahi[mt][ks], smb + XH_B + rb + 32 * ks);
            ldsm4(alo[mt][ks], smb + XL_B + rb + 32 * ks);
        }
    }
    issue_w(g_Wimg[WIMG[1]], smb, BUFB[1], tid);
    CP_COMMIT();

    // B-frag ldsm4 address offset: pair-half = lane>>4, k-half = (lane>>3)&1
    const u32 bpair = (u32)(8 * (lane >> 4) + (lane & 7)) * X_STRIDE + 16 * ((lane >> 3) & 1);

    float acc[4][8];                          // after s3 holds Q D-frags
    float* outB0 = out + (size_t)(2 * bid) * (FF * CC);

    for (int s = 0; s < 4; ++s) {
        if (s == 3) { CP_WAIT(0); } else { CP_WAIT(1); }
        __syncthreads();

        #pragma unroll
        for (int nt = 0; nt < 4; ++nt)
            #pragma unroll
            for (int j = 0; j < 8; ++j) acc[nt][j] = 0.f;

        const u32 bb = smb + BUFB[s];
        // ks-outer, chain-position-ordered MMAs: 8 independent accumulator
        // chains between RAW reuses (per-acc accumulation order unchanged).
        #pragma unroll
        for (int ks = 0; ks < 4; ++ks) {
            u32 bh[4][2], bl[4][2];
            #pragma unroll
            for (int pr = 0; pr < 2; ++pr) {   // nt pair (0,1) / (2,3)
                u32 r4[4];
                u32 ad = bb + (u32)(32 * ng + 16 * pr) * X_STRIDE + bpair + 32 * ks;
                ldsm4(r4, ad);
                bh[2 * pr][0] = r4[0]; bh[2 * pr][1] = r4[1];
                bh[2 * pr + 1][0] = r4[2]; bh[2 * pr + 1][1] = r4[3];
                ldsm4(r4, ad + 18432);
                bl[2 * pr][0] = r4[0]; bl[2 * pr][1] = r4[1];
                bl[2 * pr + 1][0] = r4[2]; bl[2 * pr + 1][1] = r4[3];
            }
            #pragma unroll
            for (int nt = 0; nt < 4; ++nt) {   // chain pos 0: ahi . bh
                mma_bf16(acc[nt],     ahi[0][ks], bh[nt]);
                mma_bf16(acc[nt] + 4, ahi[1][ks], bh[nt]);
            }
            #pragma unroll
            for (int nt = 0; nt < 4; ++nt) {   // chain pos 1: ahi . bl
                mma_bf16(acc[nt],     ahi[0][ks], bl[nt]);
                mma_bf16(acc[nt] + 4, ahi[1][ks], bl[nt]);
            }
            #pragma unroll
            for (int nt = 0; nt < 4; ++nt) {   // chain pos 2: alo . bh
                mma_bf16(acc[nt],     alo[0][ks], bh[nt]);
                mma_bf16(acc[nt] + 4, alo[1][ks], bh[nt]);
            }
        }

        if (s == 0) {
            // K -> bf16 hi|lo image [128 rows][136] (pad rows exact zeros)
            #pragma unroll
            for (int nt = 0; nt < 4; ++nt) {
                const int nb = 32 * ng + 8 * nt + 2 * l3;
                #pragma unroll
                for (int q = 0; q < 4; ++q) {
                    int r = m0 + 16 * (q >> 1) + 8 * (q & 1);
                    float va = acc[nt][4 * (q >> 1) + 2 * (q & 1)];
                    float vb = acc[nt][4 * (q >> 1) + 2 * (q & 1) + 1];
                    u32 hp = cvt_bf2(va, vb);
                    u32 lp = cvt_bf2(va - __uint_as_float(hp << 16),
                                     vb - __uint_as_float(hp & 0xffff0000u));
                    *(u32*)(smc + KH_B + (u32)r * K_STRIDE + nb * 2) = hp;
                    *(u32*)(smc + KL_B + (u32)r * K_STRIDE + nb * 2) = lp;
                }
            }
        } else if (s == 1) {
            // residual R -> gmem (epilogue RMWs it)
            #pragma unroll
            for (int nt = 0; nt < 4; ++nt) {
                const int nb = 32 * ng + 8 * nt + 2 * l3;
                #pragma unroll
                for (int q = 0; q < 4; ++q) {
                    int r = m0 + 16 * (q >> 1) + 8 * (q & 1);
                    int bt = r >> 6, f = r & 63;
                    if (f < FF) {
                        float2 v;
                        v.x = acc[nt][4 * (q >> 1) + 2 * (q & 1)];
                        v.y = acc[nt][4 * (q >> 1) + 2 * (q & 1) + 1];
                        *(float2*)(outB0 + (size_t)bt * (FF * CC) + f * CC + nb) = v;
                    }
                }
            }
        }

        if (s < 3) __syncthreads();           // buf reads done before reuse
        if (s < 2) { issue_w(g_Wimg[WIMG[s + 2]], smb, BUFB[s + 2], tid); CP_COMMIT(); }

        if (s == 2) {
            // V -> Vt^T bf16 hi|lo [bt][d][72 g]; overlays X+buf0 (both dead).
            #pragma unroll
            for (int nt = 0; nt < 4; ++nt) {
                const int n0 = 32 * ng + 8 * nt + 2 * l3;
                #pragma unroll
                for (int q = 0; q < 4; ++q) {
                    int r = m0 + 16 * (q >> 1) + 8 * (q & 1);
                    int bt = r >> 6, g = r & 63;
                    float va = acc[nt][4 * (q >> 1) + 2 * (q & 1)];
                    float vb = acc[nt][4 * (q >> 1) + 2 * (q & 1) + 1];
                    u16 ha = __bfloat16_as_ushort(__float2bfloat16(va));
                    u16 hb = __bfloat16_as_ushort(__float2bfloat16(vb));
                    u16 la = __bfloat16_as_ushort(__float2bfloat16(va - __uint_as_float((u32)ha << 16)));
                    u16 lb = __bfloat16_as_ushort(__float2bfloat16(vb - __uint_as_float((u32)hb << 16)));
                    u32 base = (u32)bt * VT_BT + (u32)g * 2;
                    *(u16*)(smc + VTH_B + base + (u32)n0 * VT_STRIDE)       = ha;
                    *(u16*)(smc + VTH_B + base + (u32)(n0 + 1) * VT_STRIDE) = hb;
                    *(u16*)(smc + VTL_B + base + (u32)n0 * VT_STRIDE)       = la;
                    *(u16*)(smc + VTL_B + base + (u32)(n0 + 1) * VT_STRIDE) = lb;
                }
            }
        }
    }
    // after s3's top sync: K image + Vt + R all visible; Q in acc. Tail barrier-free.

    // ---- scores: warp = (bt=sbt, head=ng, row-half sub); N=64 g, K=32 d
    float dS[2][8][4];
    #pragma unroll
    for (int mt = 0; mt < 2; ++mt)
        #pragma unroll
        for (int nt = 0; nt < 8; ++nt)
            #pragma unroll
            for (int j = 0; j < 4; ++j) dS[mt][nt][j] = 0.f;

    #pragma unroll
    for (int kb = 0; kb < 2; ++kb) {
        // repack Q D-frags -> bf16 hi|lo A-frags
        u32 qH[2][4], qL[2][4];
        #pragma unroll
        for (int mt = 0; mt < 2; ++mt)
            #pragma unroll
            for (int j = 0; j < 4; ++j) {
                int nt = 2 * kb + (j >> 1);
                float x0 = acc[nt][4 * mt + 2 * (j & 1)];
                float x1 = acc[nt][4 * mt + 2 * (j & 1) + 1];
                u32 hp = cvt_bf2(x0, x1);
                qH[mt][j] = hp;
                qL[mt][j] = cvt_bf2(x0 - __uint_as_float(hp << 16),
                                    x1 - __uint_as_float(hp & 0xffff0000u));
            }
        #pragma unroll
        for (int p = 0; p < 4; ++p) {
            u32 bh4[4], bl4[4];
            u32 kd = smb + KH_B
                   + (u32)(64 * sbt + 8 * (2 * p + (ii >> 1)) + (lane & 7)) * K_STRIDE
                   + 64 * ng + kb * 32 + 16 * (ii & 1);
            ldsm4(bh4, kd);
            ldsm4(bl4, kd + (KL_B - KH_B));
            // chain-position order: 4 independent accs between RAW reuses
            #pragma unroll
            for (int mt = 0; mt < 2; ++mt)
                #pragma unroll
                for (int ntl = 0; ntl < 2; ++ntl)
                    mma_bf16(dS[mt][2 * p + ntl], qH[mt], &bh4[2 * ntl]);
            #pragma unroll
            for (int mt = 0; mt < 2; ++mt)
                #pragma unroll
                for (int ntl = 0; ntl < 2; ++ntl)
                    mma_bf16(dS[mt][2 * p + ntl], qL[mt], &bh4[2 * ntl]);
            #pragma unroll
            for (int mt = 0; mt < 2; ++mt)
                #pragma unroll
                for (int ntl = 0; ntl < 2; ++ntl)
                    mma_bf16(dS[mt][2 * p + ntl], qH[mt], &bl4[2 * ntl]);
        }
    }

    // ---- softmax in fragments (mask cols >= 50)
    #pragma unroll
    for (int mt = 0; mt < 2; ++mt)
        #pragma unroll
        for (int qq = 0; qq < 2; ++qq) {
            float mx = -3.4e38f;
            #pragma unroll
            for (int nt = 0; nt < 8; ++nt)
                #pragma unroll
                for (int c = 0; c < 2; ++c) {
                    bool ok = (nt < 6) || (nt == 6 && l3 == 0);
                    if (ok) mx = fmaxf(mx, dS[mt][nt][2 * qq + c]);
                }
            mx = fmaxf(mx, __shfl_xor_sync(0xffffffffu, mx, 1));
            mx = fmaxf(mx, __shfl_xor_sync(0xffffffffu, mx, 2));
            float su = 0.f;
            #pragma unroll
            for (int nt = 0; nt < 8; ++nt)
                #pragma unroll
                for (int c = 0; c < 2; ++c) {
                    bool ok = (nt < 6) || (nt == 6 && l3 == 0);
                    float e = ok ? __expf(dS[mt][nt][2 * qq + c] - mx) : 0.f;
                    dS[mt][nt][2 * qq + c] = e;
                    su += e;
                }
            su += __shfl_xor_sync(0xffffffffu, su, 1);
            su += __shfl_xor_sync(0xffffffffu, su, 2);
            float inv = 1.0f / su;
            #pragma unroll
            for (int nt = 0; nt < 8; ++nt) {
                dS[mt][nt][2 * qq]     *= inv;
                dS[mt][nt][2 * qq + 1] *= inv;
            }
        }

    // ---- AV: lazy repack attn -> A-frags; B = Vt[sbt][d][g]; M=32,N=32,K=64
    float dV[2][4][4];
    #pragma unroll
    for (int mt = 0; mt < 2; ++mt)
        #pragma unroll
        for (int nt = 0; nt < 4; ++nt)
            #pragma unroll
            for (int j = 0; j < 4; ++j) dV[mt][nt][j] = 0.f;

    #pragma unroll
    for (int kb2 = 0; kb2 < 4; ++kb2) {
        u32 pH[2][4], pL[2][4];
        #pragma unroll
        for (int mt = 0; mt < 2; ++mt)
            #pragma unroll
            for (int j = 0; j < 4; ++j) {
                int nt = 2 * kb2 + (j >> 1);
                float x0 = dS[mt][nt][2 * (j & 1)];
                float x1 = dS[mt][nt][2 * (j & 1) + 1];
                u32 hp = cvt_bf2(x0, x1);
                pH[mt][j] = hp;
                pL[mt][j] = cvt_bf2(x0 - __uint_as_float(hp << 16),
                                    x1 - __uint_as_float(hp & 0xffff0000u));
            }
        #pragma unroll
        for (int p = 0; p < 2; ++p) {
            u32 bh4[4], bl4[4];
            u32 vd = smb + VTH_B + (u32)sbt * VT_BT
                   + (u32)(32 * ng + 8 * (2 * p + (ii >> 1)) + (lane & 7)) * VT_STRIDE
                   + kb2 * 32 + 16 * (ii & 1);
            ldsm4(bh4, vd);
            ldsm4(bl4, vd + (VTL_B - VTH_B));
            #pragma unroll
            for (int mt = 0; mt < 2; ++mt)
                #pragma unroll
                for (int ntl = 0; ntl < 2; ++ntl)
                    mma_bf16(dV[mt][2 * p + ntl], pH[mt], &bh4[2 * ntl]);
            #pragma unroll
            for (int mt = 0; mt < 2; ++mt)
                #pragma unroll
                for (int ntl = 0; ntl < 2; ++ntl)
                    mma_bf16(dV[mt][2 * p + ntl], pL[mt], &bh4[2 * ntl]);
            #pragma unroll
            for (int mt = 0; mt < 2; ++mt)
                #pragma unroll
                for (int ntl = 0; ntl < 2; ++ntl)
                    mma_bf16(dV[mt][2 * p + ntl], pH[mt], &bl4[2 * ntl]);
        }
    }

    // ---- epilogue: out = relu(AV + R)  (R pre-stored in out by stage 1)
    {
        float* outB = outB0 + (size_t)sbt * (FF * CC);
        #pragma unroll
        for (int mt = 0; mt < 2; ++mt)
            #pragma unroll
            for (int qq = 0; qq < 2; ++qq) {
                int fl = 32 * sub + 16 * mt + 8 * qq + (lane >> 2);
                if (fl < FF) {
                    #pragma unroll
                    for (int nt = 0; nt < 4; ++nt) {
                        int col = 32 * ng + 8 * nt + 2 * l3;
                        float2* p = (float2*)(outB + fl * CC + col);
                        float2 rv = *p;
                        float2 o;
                        o.x = fmaxf(dV[mt][nt][2 * qq]     + rv.x, 0.f);
                        o.y = fmaxf(dV[mt][nt][2 * qq + 1] + rv.y, 0.f);
                        *p = o;
                    }
                }
            }
    }
}

extern "C" void kernel_launch(void* const* d_in, const int* in_sizes, int n_in,
                              void* d_out, int out_size)
{
    const float* X  = (const float*)d_in[0];
    const float* Wq = (const float*)d_in[1];
    const float* Wk = (const float*)d_in[2];
    const float* Wv = (const float*)d_in[3];
    const float* Wr = (const float*)d_in[4];
    float* out = (float*)d_out;

    prep_w<<<64, 512>>>(Wq, Wk, Wv, Wr);
    cudaFuncSetAttribute(autoint_v10,
                         cudaFuncAttributeMaxDynamicSharedMemorySize, SMEM_BYTES);
    autoint_v10<<<BB / 2, 512, SMEM_BYTES>>>(X, out);
}